// round 13
// baseline (speedup 1.0000x reference)
#include <cuda_runtime.h>
#include <cuda_bf16.h>

#define BB 512
#define TT 512
#define LL 64

__device__ float g_res[BB];
__device__ unsigned int g_done = 0;   // last-CTA ticket (self-resetting)

static __device__ __forceinline__ __nv_bfloat162 asbf2(unsigned int u) {
    return *reinterpret_cast<__nv_bfloat162*>(&u);
}
static __device__ __forceinline__ float bflo(__nv_bfloat162 v) {
    unsigned int u = *reinterpret_cast<unsigned int*>(&v);
    return __uint_as_float(u << 16);
}
static __device__ __forceinline__ float bfhi(__nv_bfloat162 v) {
    unsigned int u = *reinterpret_cast<unsigned int*>(&v);
    return __uint_as_float(u & 0xFFFF0000u);
}

__global__ void __launch_bounds__(32) crf_main_kernel(
    const float* __restrict__ emission,   // [B,T,L]
    const int*   __restrict__ target,     // [B,T]
    const float* __restrict__ mask,       // [B,T]
    const float* __restrict__ start_trans,// [L]
    const float* __restrict__ trans,      // [L,L]
    const float* __restrict__ end_trans,  // [L]
    float* __restrict__ out)
{
    __shared__ float2 sm_me[TT];                       // (mask, endmask)
    __shared__ __align__(16) unsigned int sm_p[2][32]; // i-packed bf16x2 V
    __shared__ float sm_v0[2];                         // lane0's V (fp32)
    __shared__ unsigned int sm_last;

    const int b    = blockIdx.x;
    const int lane = threadIdx.x;                // owns labels 2l, 2l+1

    const float*  emb  = emission + (size_t)b * TT * LL;
    const float2* emb2 = (const float2*)emb;     // idx: t*32 + lane
    const int*    tgt  = target   + (size_t)b * TT;
    const float*  mrow = mask     + (size_t)b * TT;

    // stage (mask, end_mask)
    for (int t = lane; t < TT; t += 32) {
        float m  = mrow[t];
        float nm = (t + 1 < TT) ? mrow[t + 1] : 0.0f;
        sm_me[t] = make_float2(m, (m > nm) ? 1.0f : 0.0f);
    }

    // i-packed E columns: EpA[k]=(E[2k][2l],E[2k+1][2l]), EpB likewise for 2l+1
    __nv_bfloat162 EpA[32], EpB[32];
    #pragma unroll
    for (int k = 0; k < 32; k++) {
        const float2 r0 = ((const float2*)trans)[(2 * k)     * 32 + lane];
        const float2 r1 = ((const float2*)trans)[(2 * k + 1) * 32 + lane];
        EpA[k] = __floats2bfloat162_rn(__expf(r0.x), __expf(r1.x));
        EpB[k] = __floats2bfloat162_rn(__expf(r0.y), __expf(r1.y));
    }
    __syncwarp();

    // ---------------- path score: parallel reduction over t ----------------
    float pacc = 0.0f;
    for (int t = 1 + lane; t < TT; t += 32) {
        const int    tp = tgt[t - 1];
        const int    tc = tgt[t];
        const float2 me = sm_me[t];
        pacc += me.x * (trans[tp * LL + tc] + emb[(size_t)t * LL + tc])
              + me.y * end_trans[tc];
    }
    if (lane == 0) {
        const int t0 = tgt[0];
        pacc += start_trans[t0] + emb[t0];
    }
    #pragma unroll
    for (int o = 16; o; o >>= 1) pacc += __shfl_xor_sync(0xffffffffu, pacc, o);
    const float path_score = pacc;

    // ---------------- forward recursion in LINEAR space ----------------
    // invariant: s_j = log(V_j) + C   (C uniform across labels)
    const float2 st2 = ((const float2*)start_trans)[lane];
    const float2 et2 = ((const float2*)end_trans)[lane];
    const float  EtA = __expf(et2.x);
    const float  EtB = __expf(et2.y);
    const float2 em0 = emb2[lane];
    const float s0A = st2.x + em0.x;
    const float s0B = st2.y + em0.y;

    float C  = __shfl_sync(0xffffffffu, s0A, 0);   // C = s_{0,label0}
    float VA = __expf(s0A - C);
    float VB = __expf(s0B - C);
    {
        const __nv_bfloat162 pv = __floats2bfloat162_rn(VA, VB);
        sm_p[0][lane] = *reinterpret_cast<const unsigned int*>(&pv);
        if (lane == 0) sm_v0[0] = VA;
    }

    // emission-exp pipeline: Xc = exp(em_t) for current iter, Xn prepared ahead
    float2 em1 = emb2[1 * 32 + lane];
    float2 em2 = emb2[2 * 32 + lane];
    float XcA = __expf(em1.x);
    float XcB = __expf(em1.y);
    float prod = 1.0f;                            // pending Π V0 (log deferred)
    __syncwarp();

    for (int t = 1; t < TT; t++) {
        const float2 me = sm_me[t];

        // off-chain: lagged normalizer w = 1/V0_prev
        const float u = sm_v0[(t - 1) & 1];
        float w;
        asm("rcp.approx.f32 %0, %1;" : "=f"(w) : "f"(u));

        // off-chain: next iteration's emission exp + prefetch
        const float XnA = __expf(em2.x);
        const float XnB = __expf(em2.y);
        if (t + 2 < TT) em2 = emb2[(size_t)(t + 2) * 32 + lane];

        // dot over i for both labels: 64 HFMA2 on i-packed bf16 pairs
        const uint4* q = (const uint4*)sm_p[(t - 1) & 1];
        const __nv_bfloat162 z2 = __float2bfloat162_rn(0.0f);
        __nv_bfloat162 a0 = z2, a1 = z2, a2 = z2, a3 = z2;
        __nv_bfloat162 c0 = z2, c1 = z2, c2 = z2, c3 = z2;
        #pragma unroll
        for (int k = 0; k < 8; k++) {
            const uint4 uu = q[k];
            const __nv_bfloat162 q0 = asbf2(uu.x);
            const __nv_bfloat162 q1 = asbf2(uu.y);
            const __nv_bfloat162 q2 = asbf2(uu.z);
            const __nv_bfloat162 q3 = asbf2(uu.w);
            a0 = __hfma2(q0, EpA[4 * k + 0], a0);
            c0 = __hfma2(q0, EpB[4 * k + 0], c0);
            a1 = __hfma2(q1, EpA[4 * k + 1], a1);
            c1 = __hfma2(q1, EpB[4 * k + 1], c1);
            a2 = __hfma2(q2, EpA[4 * k + 2], a2);
            c2 = __hfma2(q2, EpB[4 * k + 2], c2);
            a3 = __hfma2(q3, EpA[4 * k + 3], a3);
            c3 = __hfma2(q3, EpB[4 * k + 3], c3);
        }
        const __nv_bfloat162 tA = __hadd2(__hadd2(a0, a1), __hadd2(a2, a3));
        const __nv_bfloat162 tB = __hadd2(__hadd2(c0, c1), __hadd2(c2, c3));
        const float dotA = bflo(tA) + bfhi(tA);
        const float dotB = bflo(tB) + bfhi(tB);

        // scale = exp(em)*w (end-bonus folded; e=1 implies m=1 for binary masks)
        const bool ebit = (me.y != 0.0f);
        const float fA = ebit ? (XcA * w) * EtA : (XcA * w);
        const float fB = ebit ? (XcB * w) * EtB : (XcB * w);

        const bool mbit = (me.x != 0.0f);
        VA = mbit ? dotA * fA : VA;
        VB = mbit ? dotB * fB : VB;
        prod *= mbit ? u : 1.0f;                  // deferred log of normalizer
        if ((t & 3) == 0) { C += __logf(prod); prod = 1.0f; }

        // publish V for next iteration
        const __nv_bfloat162 pv = __floats2bfloat162_rn(VA, VB);
        sm_p[t & 1][lane] = *reinterpret_cast<const unsigned int*>(&pv);
        if (lane == 0) sm_v0[t & 1] = VA;

        XcA = XnA; XcB = XnB;
        __syncwarp();
    }

    // final: normalizer = C + log(sum_j V_j)   (fp32, deterministic)
    C += __logf(prod);
    float sum = VA + VB;
    #pragma unroll
    for (int o = 16; o; o >>= 1) sum += __shfl_xor_sync(0xffffffffu, sum, o);

    // ---------------- fused deterministic finalization ----------------
    if (lane == 0) {
        const float norm = C + __logf(sum);
        g_res[b] = norm - path_score;
        __threadfence();
        sm_last = atomicAdd(&g_done, 1u);        // BB-1 for the last CTA
    }
    __syncwarp();
    if (sm_last == BB - 1) {
        __threadfence();                         // acquire all g_res
        float acc = 0.0f;
        #pragma unroll
        for (int k = 0; k < BB / 32; k++) acc += g_res[lane + k * 32];
        #pragma unroll
        for (int o = 16; o; o >>= 1) acc += __shfl_xor_sync(0xffffffffu, acc, o);
        if (lane == 0) {
            out[0] = acc * (1.0f / BB);
            g_done = 0;                          // reset for graph replay
        }
    }
}

extern "C" void kernel_launch(void* const* d_in, const int* in_sizes, int n_in,
                              void* d_out, int out_size) {
    const float* emission    = (const float*)d_in[0];
    const int*   target      = (const int*)  d_in[1];
    const float* mask        = (const float*)d_in[2];
    const float* start_trans = (const float*)d_in[3];
    const float* trans       = (const float*)d_in[4];
    const float* end_trans   = (const float*)d_in[5];
    float* out = (float*)d_out;

    crf_main_kernel<<<BB, 32>>>(emission, target, mask, start_trans, trans,
                                end_trans, out);
}

// round 14
// speedup vs baseline: 1.3100x; 1.3100x over previous
#include <cuda_runtime.h>
#include <cuda_bf16.h>

#define BB 512
#define TT 512
#define LL 64

__device__ float g_res[BB];
__device__ float g_fv[BB * LL];
__device__ float g_bv[BB * LL];
__device__ float g_fc[BB];
__device__ float g_bc[BB];
__device__ float g_path[BB];
__device__ unsigned int g_pair[BB];
__device__ unsigned int g_done = 0;

static __device__ __forceinline__ __nv_bfloat162 asbf2(unsigned int u) {
    return *reinterpret_cast<__nv_bfloat162*>(&u);
}
static __device__ __forceinline__ float bflo(__nv_bfloat162 v) {
    unsigned int u = *reinterpret_cast<unsigned int*>(&v);
    return __uint_as_float(u << 16);
}
static __device__ __forceinline__ float bfhi(__nv_bfloat162 v) {
    unsigned int u = *reinterpret_cast<unsigned int*>(&v);
    return __uint_as_float(u & 0xFFFF0000u);
}

// 64-label dot for two labels: q = 8 x uint4 (32 packed bf16x2 pairs),
// EA/EB = per-thread packed operand arrays. Produces fp32 dotA/dotB.
#define DOT64(q, EA, EB, dotA, dotB)                                        \
    do {                                                                    \
        const __nv_bfloat162 z2_ = __float2bfloat162_rn(0.0f);              \
        __nv_bfloat162 a0 = z2_, a1 = z2_, a2 = z2_, a3 = z2_;              \
        __nv_bfloat162 c0 = z2_, c1 = z2_, c2 = z2_, c3 = z2_;              \
        _Pragma("unroll")                                                   \
        for (int k_ = 0; k_ < 8; k_++) {                                    \
            const uint4 uu_ = (q)[k_];                                      \
            const __nv_bfloat162 q0_ = asbf2(uu_.x);                        \
            const __nv_bfloat162 q1_ = asbf2(uu_.y);                        \
            const __nv_bfloat162 q2_ = asbf2(uu_.z);                        \
            const __nv_bfloat162 q3_ = asbf2(uu_.w);                        \
            a0 = __hfma2(q0_, (EA)[4 * k_ + 0], a0);                        \
            c0 = __hfma2(q0_, (EB)[4 * k_ + 0], c0);                        \
            a1 = __hfma2(q1_, (EA)[4 * k_ + 1], a1);                        \
            c1 = __hfma2(q1_, (EB)[4 * k_ + 1], c1);                        \
            a2 = __hfma2(q2_, (EA)[4 * k_ + 2], a2);                        \
            c2 = __hfma2(q2_, (EB)[4 * k_ + 2], c2);                        \
            a3 = __hfma2(q3_, (EA)[4 * k_ + 3], a3);                        \
            c3 = __hfma2(q3_, (EB)[4 * k_ + 3], c3);                        \
        }                                                                   \
        const __nv_bfloat162 tA_ = __hadd2(__hadd2(a0, a1), __hadd2(a2, a3)); \
        const __nv_bfloat162 tB_ = __hadd2(__hadd2(c0, c1), __hadd2(c2, c3)); \
        (dotA) = bflo(tA_) + bfhi(tA_);                                     \
        (dotB) = bflo(tB_) + bfhi(tB_);                                     \
    } while (0)

__global__ void __launch_bounds__(32) crf_main_kernel(
    const float* __restrict__ emission,   // [B,T,L]
    const int*   __restrict__ target,     // [B,T]
    const float* __restrict__ mask,       // [B,T]
    const float* __restrict__ start_trans,// [L]
    const float* __restrict__ trans,      // [L,L]
    const float* __restrict__ end_trans,  // [L]
    float* __restrict__ out)
{
    __shared__ __align__(16) unsigned int sm_p[2][32]; // packed bf16x2 vectors
    __shared__ float sm_v0[2];                         // lane0's published scalar

    const int  cta   = blockIdx.x;
    const int  lane  = threadIdx.x;
    const bool isfwd = cta < BB;
    const int  b     = isfwd ? cta : cta - BB;

    const float*  emb  = emission + (size_t)b * TT * LL;
    const float2* emb2 = (const float2*)emb;     // idx: t*32 + lane
    const float*  mrow = mask + (size_t)b * TT;

    // effective length Lb (prefix binary mask), mid point
    float msum = 0.0f;
    for (int t = lane; t < TT; t += 32) msum += mrow[t];
    #pragma unroll
    for (int o = 16; o; o >>= 1) msum += __shfl_xor_sync(~0u, msum, o);
    const int Lb  = (int)(msum + 0.5f);
    const int mid = Lb >> 1;

    float C, VA, VB;
    float prod = 1.0f;

    if (isfwd) {
        // ---- forward: f_t = (E^T f_{t-1}) .* x_t ;  E columns 2l, 2l+1 ----
        __nv_bfloat162 EpA[32], EpB[32];   // packed over i-pairs
        #pragma unroll
        for (int k = 0; k < 32; k++) {
            const float2 r0 = ((const float2*)trans)[(2 * k)     * 32 + lane];
            const float2 r1 = ((const float2*)trans)[(2 * k + 1) * 32 + lane];
            EpA[k] = __floats2bfloat162_rn(__expf(r0.x), __expf(r1.x));
            EpB[k] = __floats2bfloat162_rn(__expf(r0.y), __expf(r1.y));
        }

        // path score (general masked form; exact fp32)
        float pacc = 0.0f;
        {
            const int* tgt = target + (size_t)b * TT;
            for (int t = 1 + lane; t < TT; t += 32) {
                const int   tp = tgt[t - 1];
                const int   tc = tgt[t];
                const float m  = mrow[t];
                const float nm = (t + 1 < TT) ? mrow[t + 1] : 0.0f;
                const float e  = (m > nm) ? 1.0f : 0.0f;
                pacc += m * (trans[tp * LL + tc] + emb[(size_t)t * LL + tc])
                      + e * end_trans[tc];
            }
            if (lane == 0) {
                const int t0 = tgt[0];
                pacc += start_trans[t0] + emb[t0];
            }
            #pragma unroll
            for (int o = 16; o; o >>= 1) pacc += __shfl_xor_sync(~0u, pacc, o);
        }

        const float2 st2 = ((const float2*)start_trans)[lane];
        const float2 em0 = emb2[lane];
        const float s0A = st2.x + em0.x;
        const float s0B = st2.y + em0.y;
        C  = __shfl_sync(~0u, s0A, 0);
        VA = __expf(s0A - C);
        VB = __expf(s0B - C);
        {
            const __nv_bfloat162 pv = __floats2bfloat162_rn(VA, VB);
            sm_p[0][lane] = *reinterpret_cast<const unsigned int*>(&pv);
            if (lane == 0) sm_v0[0] = VA;
        }
        float2 em1 = emb2[1 * 32 + lane];
        float2 em2 = emb2[2 * 32 + lane];
        float XcA = __expf(em1.x), XcB = __expf(em1.y);
        __syncwarp();

        for (int t = 1; t < mid; t++) {              // last computed: f_{mid-1}
            const int pb = (t - 1) & 1, cb = t & 1;
            const float u0 = sm_v0[pb];
            float w;
            asm("rcp.approx.f32 %0, %1;" : "=f"(w) : "f"(u0));
            const float XnA = __expf(em2.x);
            const float XnB = __expf(em2.y);
            if (t + 2 < TT) em2 = emb2[(size_t)(t + 2) * 32 + lane];

            const uint4* q = (const uint4*)sm_p[pb];
            float dotA, dotB;
            DOT64(q, EpA, EpB, dotA, dotB);

            VA = dotA * (XcA * w);
            VB = dotB * (XcB * w);
            prod *= u0;
            if ((t & 3) == 0) { C += __logf(prod); prod = 1.0f; }

            const __nv_bfloat162 pv = __floats2bfloat162_rn(VA, VB);
            sm_p[cb][lane] = *reinterpret_cast<const unsigned int*>(&pv);
            if (lane == 0) sm_v0[cb] = VA;
            XcA = XnA; XcB = XnB;
            __syncwarp();
        }
        C += __logf(prod);
        ((float2*)g_fv)[b * 32 + lane] = make_float2(VA, VB);
        if (lane == 0) { g_fc[b] = C; g_path[b] = pacc; }
    } else {
        // ---- backward: b_t[i] = sum_j E_ij x_{t+1,j} b_{t+1,j} ; E rows ----
        __nv_bfloat162 EpA[32], EpB[32];   // rows 2l, 2l+1 packed over j-pairs
        {
            const int iA = 2 * lane, iB = 2 * lane + 1;
            #pragma unroll
            for (int k = 0; k < 32; k++) {
                const float2 rA = ((const float2*)trans)[iA * 32 + k];
                const float2 rB = ((const float2*)trans)[iB * 32 + k];
                EpA[k] = __floats2bfloat162_rn(__expf(rA.x), __expf(rA.y));
                EpB[k] = __floats2bfloat162_rn(__expf(rB.x), __expf(rB.y));
            }
        }
        const float2 et2 = ((const float2*)end_trans)[lane];
        C  = __shfl_sync(~0u, et2.x, 0);
        VA = __expf(et2.x - C);
        VB = __expf(et2.y - C);
        {
            const float2 emT = emb2[(size_t)(Lb - 1) * 32 + lane];
            const float uA = __expf(emT.x) * VA;
            const float uB = __expf(emT.y) * VB;
            const __nv_bfloat162 pv = __floats2bfloat162_rn(uA, uB);
            sm_p[0][lane] = *reinterpret_cast<const unsigned int*>(&pv);
            if (lane == 0) sm_v0[0] = uA;
        }
        float2 em1 = emb2[(size_t)(Lb - 2) * 32 + lane];
        float2 em2 = emb2[(size_t)(Lb - 3) * 32 + lane];
        float XcA = __expf(em1.x), XcB = __expf(em1.y);
        __syncwarp();

        const int nsteps = Lb - mid;                 // t: Lb-2 down to mid-1
        for (int n = 0; n < nsteps; n++) {
            const int pb = n & 1, cb = (n + 1) & 1;
            const float u0 = sm_v0[pb];
            float w;
            asm("rcp.approx.f32 %0, %1;" : "=f"(w) : "f"(u0));
            const float XnA = __expf(em2.x);
            const float XnB = __expf(em2.y);
            const int tp2 = Lb - 4 - n;
            if (tp2 >= 0) em2 = emb2[(size_t)tp2 * 32 + lane];

            const uint4* q = (const uint4*)sm_p[pb];
            float dotA, dotB;
            DOT64(q, EpA, EpB, dotA, dotB);

            VA = dotA * w;
            VB = dotB * w;
            prod *= u0;
            if ((n & 3) == 3) { C += __logf(prod); prod = 1.0f; }

            const __nv_bfloat162 pv =
                __floats2bfloat162_rn(XcA * VA, XcB * VB);
            sm_p[cb][lane] = *reinterpret_cast<const unsigned int*>(&pv);
            if (lane == 0) sm_v0[cb] = XcA * VA;
            XcA = XnA; XcB = XnB;
            __syncwarp();
        }
        C += __logf(prod);
        ((float2*)g_bv)[b * 32 + lane] = make_float2(VA, VB);
        if (lane == 0) g_bc[b] = C;
    }

    // ---------------- per-batch combine (second finisher) ----------------
    __threadfence();
    unsigned int tk = 0;
    if (lane == 0) tk = atomicAdd(&g_pair[b], 1u);
    tk = __shfl_sync(~0u, tk, 0);
    if (tk == 1u) {
        __threadfence();                           // acquire partner's writes
        const float2 vf = ((const float2*)g_fv)[b * 32 + lane];
        const float2 vb = ((const float2*)g_bv)[b * 32 + lane];
        float s = vf.x * vb.x + vf.y * vb.y;
        #pragma unroll
        for (int o = 16; o; o >>= 1) s += __shfl_xor_sync(~0u, s, o);

        unsigned int td = 0;
        if (lane == 0) {
            const float Z = g_fc[b] + g_bc[b] + __logf(s);
            g_res[b]  = Z - g_path[b];
            g_pair[b] = 0;                         // reset for graph replay
            __threadfence();
            td = atomicAdd(&g_done, 1u);           // BB-1 for the last batch
        }
        td = __shfl_sync(~0u, td, 0);
        if (td == BB - 1) {
            __threadfence();                       // acquire all g_res
            float acc = 0.0f;
            #pragma unroll
            for (int k = 0; k < BB / 32; k++) acc += g_res[lane + k * 32];
            #pragma unroll
            for (int o = 16; o; o >>= 1) acc += __shfl_xor_sync(~0u, acc, o);
            if (lane == 0) {
                out[0] = acc * (1.0f / BB);
                g_done = 0;                        // reset for graph replay
            }
        }
    }
}

extern "C" void kernel_launch(void* const* d_in, const int* in_sizes, int n_in,
                              void* d_out, int out_size) {
    const float* emission    = (const float*)d_in[0];
    const int*   target      = (const int*)  d_in[1];
    const float* mask        = (const float*)d_in[2];
    const float* start_trans = (const float*)d_in[3];
    const float* trans       = (const float*)d_in[4];
    const float* end_trans   = (const float*)d_in[5];
    float* out = (float*)d_out;

    crf_main_kernel<<<2 * BB, 32>>>(emission, target, mask, start_trans, trans,
                                    end_trans, out);
}